// round 15
// baseline (speedup 1.0000x reference)
#include <cuda_runtime.h>
#include <cstdint>

// C51 categorical projection — scatter scan + 1D bulk-async (TMA) tile I/O,
// IN-PLACE smem tile, 64-row tiles, ~13 CTAs/SM of independent chains
// (proven best chain count; 32-row tiles were neutral-to-worse).
//
// NEW: TMA loads carry an L2::evict_first cache policy. The 111 MB probs
// read stream has zero reuse; evict-first keeps dirty OUTPUT lines resident
// in L2 so their DRAM write-back happens once (late) instead of being forced
// out mid-kernel by read thrash (~50 MB of excess DRAM traffic measured).
//
// b(j) = clamp(c + s*j, 0, 50), s = 0.99*nd, c = 2.5*(reward + 10 - 10*s).
// floor(b) nondecreasing, step in {0,1}: two live bins in registers, bin
// emitted with one predicated STS when k advances. b >= 0 after clamp, so
// (int)b == floor(b) (bit-identical, saves the floorf).
//
// Packed rows (stride 51): smem tile byte-identical to gmem tile -> whole-
// tile bulk copies; row-owner access conflict-free (bank (19t+j)%32).

constexpr int A           = 51;
constexpr int RPB         = 64;
constexpr int TILE_FLOATS = RPB * A;            // 3264
constexpr int TILE_BYTES  = TILE_FLOATS * 4;    // 13056 (multiple of 16)
constexpr int SMEM_BYTES  = 16 + TILE_BYTES;    // mbar pad + tile

__device__ __forceinline__ uint32_t smem_u32(const void* p) {
    uint32_t a;
    asm("{ .reg .u64 t; cvta.to.shared.u64 t, %1; cvt.u32.u64 %0, t; }"
        : "=r"(a) : "l"(p));
    return a;
}

__global__ __launch_bounds__(RPB, 13)
void cat_proj_kernel(const float* __restrict__ reward,
                     const float* __restrict__ probs,
                     const float* __restrict__ not_done,
                     float* __restrict__ out,
                     int bs)
{
    extern __shared__ float smraw[];            // 16B-aligned
    uint64_t* mbar = (uint64_t*)smraw;          // [0,8)
    float*    tile = smraw + 4;                 // packed [RPB][51]

    const int tid   = threadIdx.x;
    const int rbase = blockIdx.x * RPB;
    const int rows  = min(RPB, bs - rbase);
    const bool full = (rows == RPB);

    const uint32_t mbar_a = smem_u32(mbar);
    const uint32_t tile_a = smem_u32(tile);

    if (tid == 0)
        asm volatile("mbarrier.init.shared.b64 [%0], 1;" :: "r"(mbar_a) : "memory");
    __syncthreads();

    // ── stage-in: one bulk async copy with evict_first read policy
    const float* gsrc = probs + (size_t)rbase * A;
    if (full) {
        if (tid == 0) {
            uint64_t pol;
            asm volatile("createpolicy.fractional.L2::evict_first.b64 %0, 1.0;"
                         : "=l"(pol));
            asm volatile("mbarrier.arrive.expect_tx.shared.b64 _, [%0], %1;"
                         :: "r"(mbar_a), "r"((uint32_t)TILE_BYTES) : "memory");
            asm volatile(
                "cp.async.bulk.shared::cluster.global.mbarrier::complete_tx::bytes"
                ".L2::cache_hint [%0], [%1], %2, [%3], %4;"
                :: "r"(tile_a), "l"(gsrc), "r"((uint32_t)TILE_BYTES),
                   "r"(mbar_a), "l"(pol)
                : "memory");
        }
    } else {
        for (int i = tid; i < rows * A; i += RPB) tile[i] = gsrc[i];
        __syncthreads();
    }

    // ── overlap with the TMA load: per-row scalars
    const int grow = rbase + tid;
    float rw = 0.0f, nd = 0.0f;
    if (grow < bs) { rw = reward[grow]; nd = not_done[grow]; }

    // ── wait for the tile
    if (full) {
        uint32_t done = 0;
        while (!done) {
            asm volatile(
                "{ .reg .pred p; "
                "  mbarrier.try_wait.parity.shared.b64 p, [%1], %2; "
                "  selp.b32 %0, 1, 0, p; }"
                : "=r"(done) : "r"(mbar_a), "r"(0u) : "memory");
        }
    }

    // ── scan (one thread per row), in place
    if (tid < rows) {
        float* row = tile + tid * A;

        // prefetch own row to registers
        float pv[A];
        #pragma unroll
        for (int j = 0; j < A; j++) pv[j] = row[j];

        // zero own row in place (reads done)
        #pragma unroll
        for (int j = 0; j < A; j++) row[j] = 0.0f;

        const float s = 0.99f * nd;
        const float c = 2.5f * (rw + 10.0f - 10.0f * s);

        float b  = fminf(fmaxf(c, 0.0f), 50.0f);
        int   k  = (int)b;                    // b>=0: trunc == floor
        float lf = (float)k;
        float wu = (b - lf) * pv[0];
        float aK  = pv[0] - wu;
        float aK1 = wu;

        #pragma unroll
        for (int j = 1; j < A; j++) {
            b = fminf(fmaxf(fmaf(s, (float)j, c), 0.0f), 50.0f);
            int li = (int)b;                  // in {k, k+1}
            lf = (float)li;
            wu = (b - lf) * pv[j];
            float wl = pv[j] - wu;

            bool adv = (li != k);
            if (adv) row[k] = aK;             // predicated single STS
            aK  = adv ? aK1  : aK;
            aK1 = adv ? 0.0f : aK1;
            k   = li;

            aK  += wl;
            aK1 += wu;
        }
        int k1 = k + 1; if (k1 > A - 1) k1 = A - 1;
        row[k1] = aK1;                         // if k==50, aK1==0: benign
        row[k]  = aK;
    }
    __syncthreads();

    // ── copy-out: one bulk async store (default policy: let writes linger)
    float* gdst = out + (size_t)rbase * A;
    if (full) {
        if (tid == 0) {
            asm volatile("fence.proxy.async.shared::cta;" ::: "memory");
            asm volatile(
                "cp.async.bulk.global.shared::cta.bulk_group [%0], [%1], %2;"
                :: "l"(gdst), "r"(tile_a), "r"((uint32_t)TILE_BYTES) : "memory");
            asm volatile("cp.async.bulk.commit_group;" ::: "memory");
            asm volatile("cp.async.bulk.wait_group 0;" ::: "memory");
        }
    } else {
        for (int i = tid; i < rows * A; i += RPB) gdst[i] = tile[i];
    }
}

extern "C" void kernel_launch(void* const* d_in, const int* in_sizes, int n_in,
                              void* d_out, int out_size)
{
    const float* reward   = (const float*)d_in[0];
    const float* probs    = (const float*)d_in[1];
    const float* not_done = (const float*)d_in[2];
    float* out = (float*)d_out;

    const int bs   = in_sizes[0];
    const int grid = (bs + RPB - 1) / RPB;

    cudaFuncSetAttribute(cat_proj_kernel,
                         cudaFuncAttributeMaxDynamicSharedMemorySize,
                         SMEM_BYTES);
    cat_proj_kernel<<<grid, RPB, SMEM_BYTES>>>(reward, probs, not_done, out, bs);
}

// round 17
// speedup vs baseline: 1.1174x; 1.1174x over previous
#include <cuda_runtime.h>
#include <cstdint>

// C51 categorical projection — scatter scan + 1D bulk-async (TMA) tile I/O,
// IN-PLACE smem tile, 64-row tiles, 14 CTAs/SM of independent
// load/scan/store chains. (R15's L2 evict_first hint REGRESSED 28.4->38.2us
// kernel — reverted; default cache policy restored.)
//
// Store tail uses cp.async.bulk.wait_group.READ (smem read-out only, the
// CUTLASS tma_store_wait pattern): CTA exit doesn't need DRAM visibility,
// so the store's global round-trip leaves the critical path.
//
// b(j) = clamp(c + s*j, 0, 50), s = 0.99*nd, c = 2.5*(reward + 10 - 10*s).
// floor(b) nondecreasing, step in {0,1}: two live bins in registers, bin
// emitted with one predicated STS when k advances. b >= 0 after clamp, so
// (int)b == floor(b) (bit-identical, saves the floorf).
//
// Packed rows (stride 51): smem tile byte-identical to gmem tile -> whole-
// tile bulk copies; row-owner access conflict-free (bank (19t+j)%32,
// gcd(19,32)=1 => lane bijection).

constexpr int A           = 51;
constexpr int RPB         = 64;
constexpr int TILE_FLOATS = RPB * A;            // 3264
constexpr int TILE_BYTES  = TILE_FLOATS * 4;    // 13056 (multiple of 16)
constexpr int SMEM_BYTES  = 16 + TILE_BYTES;    // mbar pad + tile

__device__ __forceinline__ uint32_t smem_u32(const void* p) {
    uint32_t a;
    asm("{ .reg .u64 t; cvta.to.shared.u64 t, %1; cvt.u32.u64 %0, t; }"
        : "=r"(a) : "l"(p));
    return a;
}

__global__ __launch_bounds__(RPB, 14)
void cat_proj_kernel(const float* __restrict__ reward,
                     const float* __restrict__ probs,
                     const float* __restrict__ not_done,
                     float* __restrict__ out,
                     int bs)
{
    extern __shared__ float smraw[];            // 16B-aligned
    uint64_t* mbar = (uint64_t*)smraw;          // [0,8)
    float*    tile = smraw + 4;                 // packed [RPB][51]

    const int tid   = threadIdx.x;
    const int rbase = blockIdx.x * RPB;
    const int rows  = min(RPB, bs - rbase);
    const bool full = (rows == RPB);

    const uint32_t mbar_a = smem_u32(mbar);
    const uint32_t tile_a = smem_u32(tile);

    if (tid == 0)
        asm volatile("mbarrier.init.shared.b64 [%0], 1;" :: "r"(mbar_a) : "memory");
    __syncthreads();

    // ── stage-in: one bulk async copy (full blocks), scalar fallback (tail)
    const float* gsrc = probs + (size_t)rbase * A;
    if (full) {
        if (tid == 0) {
            asm volatile("mbarrier.arrive.expect_tx.shared.b64 _, [%0], %1;"
                         :: "r"(mbar_a), "r"((uint32_t)TILE_BYTES) : "memory");
            asm volatile(
                "cp.async.bulk.shared::cluster.global.mbarrier::complete_tx::bytes "
                "[%0], [%1], %2, [%3];"
                :: "r"(tile_a), "l"(gsrc), "r"((uint32_t)TILE_BYTES), "r"(mbar_a)
                : "memory");
        }
    } else {
        for (int i = tid; i < rows * A; i += RPB) tile[i] = gsrc[i];
        __syncthreads();
    }

    // ── overlap with the TMA load: per-row scalars
    const int grow = rbase + tid;
    float rw = 0.0f, nd = 0.0f;
    if (grow < bs) { rw = reward[grow]; nd = not_done[grow]; }

    // ── wait for the tile
    if (full) {
        uint32_t done = 0;
        while (!done) {
            asm volatile(
                "{ .reg .pred p; "
                "  mbarrier.try_wait.parity.shared.b64 p, [%1], %2; "
                "  selp.b32 %0, 1, 0, p; }"
                : "=r"(done) : "r"(mbar_a), "r"(0u) : "memory");
        }
    }

    // ── scan (one thread per row), in place
    if (tid < rows) {
        float* row = tile + tid * A;

        // prefetch own row to registers
        float pv[A];
        #pragma unroll
        for (int j = 0; j < A; j++) pv[j] = row[j];

        // zero own row in place (reads done)
        #pragma unroll
        for (int j = 0; j < A; j++) row[j] = 0.0f;

        const float s = 0.99f * nd;
        const float c = 2.5f * (rw + 10.0f - 10.0f * s);

        float b  = fminf(fmaxf(c, 0.0f), 50.0f);
        int   k  = (int)b;                    // b>=0: trunc == floor
        float lf = (float)k;
        float wu = (b - lf) * pv[0];
        float aK  = pv[0] - wu;
        float aK1 = wu;

        #pragma unroll
        for (int j = 1; j < A; j++) {
            b = fminf(fmaxf(fmaf(s, (float)j, c), 0.0f), 50.0f);
            int li = (int)b;                  // in {k, k+1}
            lf = (float)li;
            wu = (b - lf) * pv[j];
            float wl = pv[j] - wu;

            bool adv = (li != k);
            if (adv) row[k] = aK;             // predicated single STS
            aK  = adv ? aK1  : aK;
            aK1 = adv ? 0.0f : aK1;
            k   = li;

            aK  += wl;
            aK1 += wu;
        }
        int k1 = k + 1; if (k1 > A - 1) k1 = A - 1;
        row[k1] = aK1;                         // if k==50, aK1==0: benign
        row[k]  = aK;
    }
    __syncthreads();

    // ── copy-out: one bulk async store; only wait for smem READ-OUT before
    //    exit (TMA unit completes the global write independently)
    float* gdst = out + (size_t)rbase * A;
    if (full) {
        if (tid == 0) {
            asm volatile("fence.proxy.async.shared::cta;" ::: "memory");
            asm volatile(
                "cp.async.bulk.global.shared::cta.bulk_group [%0], [%1], %2;"
                :: "l"(gdst), "r"(tile_a), "r"((uint32_t)TILE_BYTES) : "memory");
            asm volatile("cp.async.bulk.commit_group;" ::: "memory");
            asm volatile("cp.async.bulk.wait_group.read 0;" ::: "memory");
        }
    } else {
        for (int i = tid; i < rows * A; i += RPB) gdst[i] = tile[i];
    }
}

extern "C" void kernel_launch(void* const* d_in, const int* in_sizes, int n_in,
                              void* d_out, int out_size)
{
    const float* reward   = (const float*)d_in[0];
    const float* probs    = (const float*)d_in[1];
    const float* not_done = (const float*)d_in[2];
    float* out = (float*)d_out;

    const int bs   = in_sizes[0];
    const int grid = (bs + RPB - 1) / RPB;

    cudaFuncSetAttribute(cat_proj_kernel,
                         cudaFuncAttributeMaxDynamicSharedMemorySize,
                         SMEM_BYTES);
    cat_proj_kernel<<<grid, RPB, SMEM_BYTES>>>(reward, probs, not_done, out, bs);
}